// round 12
// baseline (speedup 1.0000x reference)
#include <cuda_runtime.h>
#include <cuda_bf16.h>
#include <cstdint>
#include <math.h>

// ---------------- problem constants ----------------
#define D_MODEL   1024
#define NUM_TILES 64
#define TPC       8
#define NUM_CL    8
#define COMP_H    256
#define GRIDW     16
#define EPS_LN    1e-5f

// ---------------- GEMM config ----------------
#define NCOL_PAD  384              // 48 n8-tiles (256 hidden + 8 cluster + 64 tile + 56 pad)
#define M_BLK     64
#define KC        64
#define NCHUNK    (D_MODEL / KC)   // 16
#define ROWB      144              // 128B k-data + 16B pad; ldmatrix conflict-free
#define CSTRIDE   388              // float4-aligned rows, 4-bank row shift
#define NTHREADS  512

#define A_BYTES      (M_BLK * ROWB)           // 9216
#define B_BYTES      (NCOL_PAD * ROWB)        // 55296
#define STAGE_BYTES  (A_BYTES + B_BYTES)      // 64512
#define B_SEGS       (NCOL_PAD * 8)           // 3072 16B-segs per chunk
#define PARAM_OFF    (2 * STAGE_BYTES)        // 129024 (Csm 99328 aliases stages)
#define SMEM_TOTAL   (PARAM_OFF + 3 * COMP_H * 4)   // 132096

// Wcat, chunk-major: [chunk][row n][k within chunk]
__device__ __nv_bfloat16 g_Wcat[NCHUNK][NCOL_PAD][KC];

// ---------------- merged prep: W1 transpose + signatures + pad --------------
__global__ void prep_kernel(const float* __restrict__ w1,
                            const float* __restrict__ raw) {
    __shared__ float t[32][33];
    const int b = blockIdx.x;
    if (b < 256) {
        const int tx = threadIdx.x & 31, ty = threadIdx.x >> 5;   // 32 x 8
        const int n0 = (b & 7) * 32, k0 = (b >> 3) * 32;
        #pragma unroll
        for (int r = 0; r < 4; ++r) {
            int k = k0 + ty + r * 8;
            t[ty + r * 8][tx] = w1[(size_t)k * COMP_H + n0 + tx];
        }
        __syncthreads();
        #pragma unroll
        for (int r = 0; r < 4; ++r) {
            int n = n0 + ty + r * 8;
            int k = k0 + tx;
            g_Wcat[k >> 6][n][k & 63] = __float2bfloat16(t[tx][ty + r * 8]);
        }
    } else {
        const int nn = b - 256;          // 0..127 -> n = 256..383
        const int n = COMP_H + nn;
        #pragma unroll
        for (int r = 0; r < 4; ++r) {
            int k = threadIdx.x + r * 256;
            float val;
            if (nn < NUM_CL) {
                float s = 0.f;
                #pragma unroll
                for (int j = 0; j < TPC; ++j) {
                    float rv = raw[(size_t)(nn * TPC + j) * D_MODEL + k];
                    s += (rv > 0.3f) ? 1.f : ((rv < -0.3f) ? -1.f : 0.f);
                }
                val = (s > 0.f) ? 1.f : ((s < 0.f) ? -1.f : 0.f);
            } else if (nn < NUM_CL + NUM_TILES) {
                float rv = raw[(size_t)(nn - NUM_CL) * D_MODEL + k];
                val = (rv > 0.3f) ? 1.f : ((rv < -0.3f) ? -1.f : 0.f);
            } else {
                val = 0.f;
            }
            g_Wcat[k >> 6][n][k & 63] = __float2bfloat16(val);
        }
    }
}

// ---------------- helpers ----------------
__device__ __forceinline__ float gelu_exact(float v) {
    return 0.5f * v * (1.0f + erff(v * 0.7071067811865476f));
}
__device__ __forceinline__ void mma16816(float c[4], const uint32_t a[4],
                                         uint32_t b0, uint32_t b1) {
    asm volatile(
        "mma.sync.aligned.m16n8k16.row.col.f32.bf16.bf16.f32 "
        "{%0,%1,%2,%3}, {%4,%5,%6,%7}, {%8,%9}, {%0,%1,%2,%3};\n"
        : "+f"(c[0]), "+f"(c[1]), "+f"(c[2]), "+f"(c[3])
        : "r"(a[0]), "r"(a[1]), "r"(a[2]), "r"(a[3]), "r"(b0), "r"(b1));
}
__device__ __forceinline__ void ldsm_x4(uint32_t* r, uint32_t addr) {
    asm volatile("ldmatrix.sync.aligned.m8n8.x4.shared.b16 {%0,%1,%2,%3}, [%4];"
                 : "=r"(r[0]), "=r"(r[1]), "=r"(r[2]), "=r"(r[3]) : "r"(addr));
}
__device__ __forceinline__ void cp16cg(uint32_t dst, const void* src) {
    asm volatile("cp.async.cg.shared.global [%0], [%1], 16;\n" :: "r"(dst), "l"(src));
}
__device__ __forceinline__ void warp_argmax(float& v, int& i) {
    #pragma unroll
    for (int o = 16; o; o >>= 1) {
        float ov = __shfl_xor_sync(0xffffffffu, v, o);
        int   oi = __shfl_xor_sync(0xffffffffu, i, o);
        if (ov > v || (ov == v && oi < i)) { v = ov; i = oi; }
    }
}
__device__ __forceinline__ float warp_sum(float v) {
    #pragma unroll
    for (int o = 16; o; o >>= 1) v += __shfl_xor_sync(0xffffffffu, v, o);
    return v;
}
__device__ __forceinline__ uint32_t as_u32(__nv_bfloat162 h) {
    return *reinterpret_cast<uint32_t*>(&h);
}

// ---------------- main fused kernel ----------------
__global__ void __launch_bounds__(NTHREADS)
fused_kernel(const float* __restrict__ X,
             const float* __restrict__ cb1,
             const float* __restrict__ cw2,
             const float* __restrict__ cb2,
             const float* __restrict__ sw1,
             const float* __restrict__ sb1,
             const float* __restrict__ sw2,
             const float* __restrict__ sb2,
             const float* __restrict__ dirs,
             const float* __restrict__ gamma,
             const float* __restrict__ beta,
             const float* __restrict__ oscale_p,
             float* __restrict__ out) {
    extern __shared__ char sm[];
    float* Csm  = (float*)sm;
    float* b1c  = (float*)(sm + PARAM_OFF);
    float* w2c0 = b1c + COMP_H;
    float* w2c1 = w2c0 + COMP_H;
    const uint32_t smem_u32 = (uint32_t)__cvta_generic_to_shared(sm);

    const int tid  = threadIdx.x;
    const int lane = tid & 31;
    const int wid  = tid >> 5;      // 0..15
    const int mw   = wid & 1;       // 2 m-groups of 32 rows
    const int nw   = wid >> 1;      // 8 n-groups of 48 cols (6 n8-tiles)
    const int r0   = blockIdx.x * M_BLK;

    if (tid < COMP_H) {
        b1c[tid]  = cb1[tid];
        w2c0[tid] = cw2[tid * 2 + 0];
        w2c1[tid] = cw2[tid * 2 + 1];
    }
    const float oscale = oscale_p[0];
    const float b2_0 = cb2[0];
    const float b2_1 = cb2[1];

    float acc[2][6][4];
    #pragma unroll
    for (int mt = 0; mt < 2; ++mt)
        #pragma unroll
        for (int nt = 0; nt < 6; ++nt)
            #pragma unroll
            for (int j = 0; j < 4; ++j) acc[mt][nt][j] = 0.f;

    const float4* X4 = (const float4*)X;
    const int arow = tid >> 3, asg = tid & 7;      // A-fill: 512 segs of 16B

    // per-warp ldmatrix offsets (within a stage)
    const uint32_t a_lm0 = (uint32_t)((mw * 32 + (lane & 15)) * ROWB + (lane >> 4) * 16);
    const uint32_t a_lm1 = a_lm0 + 16u * ROWB;
    const uint32_t b_lm4 = (uint32_t)((((lane >> 4) & 1) * 8 + (lane & 7)) * ROWB
                                      + ((lane >> 3) & 1) * 16);

    auto fill_B = [&](int kc, int stage) {
        const char* src = (const char*)&g_Wcat[kc][0][0];
        uint32_t bb = smem_u32 + stage * STAGE_BYTES + A_BYTES;
        #pragma unroll
        for (int rep = 0; rep < 6; ++rep) {
            int s = tid + rep * NTHREADS;        // exactly B_SEGS = 3072
            cp16cg(bb + (s >> 3) * ROWB + (s & 7) * 16, src + s * 16);
        }
        asm volatile("cp.async.commit_group;\n");
    };
    auto store_A = [&](const float4& v0, const float4& v1, int stage) {
        uint4 hh = make_uint4(as_u32(__floats2bfloat162_rn(v0.x, v0.y)),
                              as_u32(__floats2bfloat162_rn(v0.z, v0.w)),
                              as_u32(__floats2bfloat162_rn(v1.x, v1.y)),
                              as_u32(__floats2bfloat162_rn(v1.z, v1.w)));
        *(uint4*)(sm + stage * STAGE_BYTES + arow * ROWB + asg * 16) = hh;
    };

    // ---- prologue: stage 0 <- chunk 0 ----
    {
        fill_B(0, 0);
        const float4* p = X4 + (size_t)(r0 + arow) * (D_MODEL / 4) + asg * 2;
        float4 v0 = p[0], v1 = p[1];
        store_A(v0, v1, 0);
        asm volatile("cp.async.wait_group 0;\n");
        __syncthreads();
    }

    // ---- pipelined mainloop ----
    for (int kc = 0; kc < NCHUNK; ++kc) {
        const int cur = kc & 1, nxt = cur ^ 1;
        const bool has_next = (kc + 1 < NCHUNK);
        const uint32_t sb = smem_u32 + cur * STAGE_BYTES;

        float4 v0, v1;
        if (has_next) {
            const float4* p = X4 + (size_t)(r0 + arow) * (D_MODEL / 4)
                              + (kc + 1) * (KC / 4) + asg * 2;
            v0 = p[0]; v1 = p[1];
            fill_B(kc + 1, nxt);
        }

        // MMA block: cross-kstep software-pipelined LDSM
        {
            const uint32_t bb0 = sb + A_BYTES + (uint32_t)(nw * 48 * ROWB);
            uint32_t A0c[4], A1c[4], A0n[4], A1n[4], Bc[4], Bn[4];
            ldsm_x4(A0c, sb + a_lm0);
            ldsm_x4(A1c, sb + a_lm1);
            ldsm_x4(Bc, bb0 + b_lm4);
            #pragma unroll
            for (int ks = 0; ks < 4; ++ks) {
                const uint32_t bbase = bb0 + ks * 32;
                #pragma unroll
                for (int p = 0; p < 3; ++p) {
                    if (p < 2) {
                        ldsm_x4(Bn, bbase + b_lm4 + (uint32_t)((p + 1) * 16 * ROWB));
                    } else if (ks < 3) {
                        ldsm_x4(A0n, sb + a_lm0 + (ks + 1) * 32);
                        ldsm_x4(A1n, sb + a_lm1 + (ks + 1) * 32);
                        ldsm_x4(Bn, bb0 + (ks + 1) * 32 + b_lm4);
                    }
                    mma16816(acc[0][2 * p],     A0c, Bc[0], Bc[1]);
                    mma16816(acc[1][2 * p],     A1c, Bc[0], Bc[1]);
                    mma16816(acc[0][2 * p + 1], A0c, Bc[2], Bc[3]);
                    mma16816(acc[1][2 * p + 1], A1c, Bc[2], Bc[3]);
                    #pragma unroll
                    for (int j = 0; j < 4; ++j) Bc[j] = Bn[j];
                    if (p == 2 && ks < 3) {
                        #pragma unroll
                        for (int j = 0; j < 4; ++j) { A0c[j] = A0n[j]; A1c[j] = A1n[j]; }
                    }
                }
            }
        }

        if (has_next) store_A(v0, v1, nxt);
        asm volatile("cp.async.wait_group 0;\n");
        __syncthreads();
    }

    // ---- dump C to smem (stages dead now) ----
    #pragma unroll
    for (int mt = 0; mt < 2; ++mt)
        #pragma unroll
        for (int nt = 0; nt < 6; ++nt) {
            int cr = mw * 32 + mt * 16 + (lane >> 2);
            int cc = (nw * 6 + nt) * 8 + (lane & 3) * 2;
            *(float2*)&Csm[cr * CSTRIDE + cc] =
                make_float2(acc[mt][nt][0], acc[mt][nt][1]);
            *(float2*)&Csm[(cr + 8) * CSTRIDE + cc] =
                make_float2(acc[mt][nt][2], acc[mt][nt][3]);
        }
    __syncthreads();

    // ---- epilogue: one warp per token, 4 tokens per warp ----
    for (int it = 0; it < 4; ++it) {
        const int m = wid * 4 + it;
        const int r = r0 + m;
        const float* crow = Csm + m * CSTRIDE;
        const float4* crow4 = (const float4*)crow;
        const float4* b1c4  = (const float4*)b1c;
        const float4* w2c04 = (const float4*)w2c0;
        const float4* w2c14 = (const float4*)w2c1;

        float s0 = 0.f, s1 = 0.f;
        #pragma unroll
        for (int jj = 0; jj < 2; ++jj) {
            int j = lane + jj * 32;
            float4 c = crow4[j], b = b1c4[j], wa = w2c04[j], wb = w2c14[j];
            float h;
            h = gelu_exact(c.x + b.x); s0 += h * wa.x; s1 += h * wb.x;
            h = gelu_exact(c.y + b.y); s0 += h * wa.y; s1 += h * wb.y;
            h = gelu_exact(c.z + b.z); s0 += h * wa.z; s1 += h * wb.z;
            h = gelu_exact(c.w + b.w); s0 += h * wa.w; s1 += h * wb.w;
        }
        s0 = warp_sum(s0);
        s1 = warp_sum(s1);
        float comp0 = tanhf(s0 + b2_0);
        float comp1 = tanhf(s1 + b2_1);

        // routing (calibration monotone -> argmax of raw scores)
        float cv = -INFINITY; int ci = 1 << 20;
        if (lane < NUM_CL) { cv = crow[COMP_H + lane]; ci = lane; }
        warp_argmax(cv, ci);
        float tv = -INFINITY; int tl = 1 << 20;
        if (lane < TPC) { tv = crow[COMP_H + NUM_CL + ci * TPC + lane]; tl = lane; }
        warp_argmax(tv, tl);
        const int tile = ci * TPC + tl;

        // tiny spline MLP
        float contrib = 0.f;
        if (lane < GRIDW) {
            int g = lane;
            float hw = comp0 * sw1[tile * 32 + g] + comp1 * sw1[tile * 32 + 16 + g]
                       + sb1[tile * 16 + g];
            hw = fmaxf(hw, 0.f);
            contrib = hw * sw2[tile * 16 + g];
        }
        float mag = warp_sum(contrib) + sb2[tile];
        const float factor = mag * oscale;

        // residual + layernorm (fp32 exact); recompute y on write pass (L1-hot)
        const float4* xr4 = (const float4*)(X + (size_t)r * D_MODEL);
        const float4* dr4 = (const float4*)(dirs + (size_t)tile * D_MODEL);
        const float4* g4  = (const float4*)gamma;
        const float4* be4 = (const float4*)beta;
        float4* o4 = (float4*)(out + (size_t)r * D_MODEL);
        float sum = 0.f, sumsq = 0.f;
        #pragma unroll
        for (int ii = 0; ii < 8; ++ii) {
            int i = lane + ii * 32;
            float4 xv = xr4[i], dv = dr4[i];
            float yx = xv.x + factor * dv.x;
            float yy = xv.y + factor * dv.y;
            float yz = xv.z + factor * dv.z;
            float yw = xv.w + factor * dv.w;
            sum   += yx + yy + yz + yw;
            sumsq += yx * yx + yy * yy + yz * yz + yw * yw;
        }
        sum   = warp_sum(sum);
        sumsq = warp_sum(sumsq);
        const float mu   = sum * (1.f / D_MODEL);
        const float var  = sumsq * (1.f / D_MODEL) - mu * mu;
        const float rstd = rsqrtf(var + EPS_LN);
        #pragma unroll
        for (int ii = 0; ii < 8; ++ii) {
            int i = lane + ii * 32;
            float4 xv = xr4[i], dv = dr4[i], gv = g4[i], bv = be4[i], o;
            o.x = (xv.x + factor * dv.x - mu) * rstd * gv.x + bv.x;
            o.y = (xv.y + factor * dv.y - mu) * rstd * gv.y + bv.y;
            o.z = (xv.z + factor * dv.z - mu) * rstd * gv.z + bv.z;
            o.w = (xv.w + factor * dv.w - mu) * rstd * gv.w + bv.w;
            o4[i] = o;
        }
    }
}

// ---------------- launch ----------------
extern "C" void kernel_launch(void* const* d_in, const int* in_sizes, int n_in,
                              void* d_out, int out_size) {
    const float* x      = (const float*)d_in[0];
    const float* sraw   = (const float*)d_in[1];
    // d_in[2] knot_values, d_in[3] temperature: unused (calibration monotone)
    const float* cw1    = (const float*)d_in[4];
    const float* cb1    = (const float*)d_in[5];
    const float* cw2    = (const float*)d_in[6];
    const float* cb2    = (const float*)d_in[7];
    const float* sw1    = (const float*)d_in[8];
    const float* sb1    = (const float*)d_in[9];
    const float* sw2    = (const float*)d_in[10];
    const float* sb2    = (const float*)d_in[11];
    const float* dirs   = (const float*)d_in[12];
    const float* gamma  = (const float*)d_in[13];
    const float* beta   = (const float*)d_in[14];
    const float* oscale = (const float*)d_in[15];
    float* out = (float*)d_out;

    const int N = in_sizes[0] / D_MODEL;     // 16384
    const int nblocks = N / M_BLK;           // 256

    cudaFuncSetAttribute(fused_kernel,
                         cudaFuncAttributeMaxDynamicSharedMemorySize, SMEM_TOTAL);

    prep_kernel<<<384, 256>>>(cw1, sraw);
    fused_kernel<<<nblocks, NTHREADS, SMEM_TOTAL>>>(
        x, cb1, cw2, cb2, sw1, sb1, sw2, sb2, dirs, gamma, beta, oscale, out);
}